// round 8
// baseline (speedup 1.0000x reference)
#include <cuda_runtime.h>

// Attention_72447508349519 — algebraic collapse:
//   softmax rows sum to 1 and einsum('bqk,bvd->bqd') contracts k and v
//   independently, so out[b,q,d] = sum_n v[b,n,d] for every q.
//   Pipeline: k1 (stats + gamma-weighted colsums, contiguous-line layout) ->
//   k2 (fold groups -> s) -> k3 (GEMV Wv) -> k4a (GEMV Wo) ->
//   k4b (pure 64MB broadcast store, minimal serial prologue).
// Unused inputs: Wq,bq,Wk,bk.

#define BSZ   16
#define CDIM  1024
#define NPOS  1024
#define NGRP  32
#define GROWS 32
#define EPS   1e-5f

__device__ float g_P[BSZ * NGRP * CDIM];     // P[b,g,c]
__device__ float g_partS[BSZ * NGRP * 4];    // per-(b,g,ctile) sum
__device__ float g_partQ[BSZ * NGRP * 4];    // per-(b,g,ctile) sumsq
__device__ float g_s[BSZ * CDIM];
__device__ float g_vsum[BSZ * CDIM];
__device__ float g_y[BSZ * CDIM];

// ---------------------------------------------------------------------------
// k1: thread = channel. Key fact: group g of channel c is 32 CONTIGUOUS
// floats (one 128B line) at x[b, c, 32g..32g+32). Each thread handles 4
// groups x 8 float4 from its own lines -> no cross-lane partials, no smem
// round-trip, no hot-loop shuffles. gamma chunk broadcast from smem.
// grid (4 ctiles, 8 gtiles, 16 b) = 512 CTAs x 256 thr.
// ---------------------------------------------------------------------------
__global__ __launch_bounds__(256) void k1_stats(const float* __restrict__ x,
                                                const float* __restrict__ gamma) {
    const int ct = blockIdx.x;      // channel tile: c in [256*ct, 256*ct+256)
    const int gt = blockIdx.y;      // group tile: g in [4*gt, 4*gt+4)
    const int b  = blockIdx.z;
    const int tid = threadIdx.x;
    const int c = ct * 256 + tid;

    __shared__ float4 sg4[32];      // gamma[128*gt .. +128) as float4
    __shared__ float sredS[4][8], sredQ[4][8];
    if (tid < 32) sg4[tid] = reinterpret_cast<const float4*>(gamma + gt * 128)[tid];
    __syncthreads();

    const float4* xrow = reinterpret_cast<const float4*>(
        x + (size_t)b * CDIM * NPOS + (size_t)c * NPOS + gt * 128);

    float pw[4], ts[4], tq[4];
    #pragma unroll
    for (int gg = 0; gg < 4; gg++) {
        float4 xa[8];
        #pragma unroll
        for (int j = 0; j < 8; j++) xa[j] = xrow[gg * 8 + j];
        float s = 0.f, q = 0.f, p = 0.f;
        #pragma unroll
        for (int j = 0; j < 8; j++) {
            const float4 v = xa[j];
            const float4 w = sg4[gg * 8 + j];
            s += (v.x + v.y) + (v.z + v.w);
            q += (v.x * v.x + v.y * v.y) + (v.z * v.z + v.w * v.w);
            p += w.x * v.x + w.y * v.y + w.z * v.z + w.w * v.w;
        }
        pw[gg] = p; ts[gg] = s; tq[gg] = q;
    }

    // Coalesced P stores (warp = 32 consecutive channels).
    #pragma unroll
    for (int gg = 0; gg < 4; gg++)
        g_P[(b * NGRP + gt * 4 + gg) * CDIM + c] = pw[gg];

    // Reduce per-group sum/sumsq over the 256 threads (one ctile's partial).
    const int wid = tid >> 5, lane = tid & 31;
    #pragma unroll
    for (int gg = 0; gg < 4; gg++) {
        float s = ts[gg], q = tq[gg];
        #pragma unroll
        for (int o = 16; o; o >>= 1) {
            s += __shfl_xor_sync(0xFFFFFFFFu, s, o);
            q += __shfl_xor_sync(0xFFFFFFFFu, q, o);
        }
        if (lane == 0) { sredS[gg][wid] = s; sredQ[gg][wid] = q; }
    }
    __syncthreads();
    if (tid < 4) {
        float S = 0.f, Q = 0.f;
        #pragma unroll
        for (int w = 0; w < 8; w++) { S += sredS[tid][w]; Q += sredQ[tid][w]; }
        const int g = gt * 4 + tid;
        g_partS[(b * NGRP + g) * 4 + ct] = S;
        g_partQ[(b * NGRP + g) * 4 + ct] = Q;
    }
}

// ---------------------------------------------------------------------------
// k2: fold ctile partials -> mean/rstd, then
//     s[b,c] = sum_g rstd[b,g]*(P[b,g,c] - mean[b,g]*Gam_g) + sum_n beta[n]
// ---------------------------------------------------------------------------
__global__ __launch_bounds__(1024) void k2_colsum(const float* __restrict__ gamma,
                                                  const float* __restrict__ beta) {
    const int b = blockIdx.x;
    const int tid = threadIdx.x;

    __shared__ float sgam[CDIM];
    __shared__ float sGam[NGRP];
    __shared__ float sm[NGRP], sr[NGRP];
    __shared__ float redb[32];
    __shared__ float sB;

    sgam[tid] = gamma[tid];
    float bb = beta[tid];
    #pragma unroll
    for (int o = 16; o; o >>= 1) bb += __shfl_xor_sync(0xFFFFFFFFu, bb, o);
    const int wid = tid >> 5, lane = tid & 31;
    if (lane == 0) redb[wid] = bb;

    if (tid < NGRP) {
        float S = 0.f, Q = 0.f;
        #pragma unroll
        for (int ct = 0; ct < 4; ct++) {
            S += g_partS[(b * NGRP + tid) * 4 + ct];
            Q += g_partQ[(b * NGRP + tid) * 4 + ct];
        }
        const float inv = 1.f / (float)(GROWS * CDIM);
        const float m = S * inv;
        const float var = Q * inv - m * m;
        sm[tid] = m;
        sr[tid] = rsqrtf(var + EPS);
    }
    __syncthreads();

    if (tid < NGRP) {
        float t = 0.f;
        #pragma unroll
        for (int j = 0; j < GROWS; j++) t += sgam[tid * GROWS + j];
        sGam[tid] = t;
    }
    if (tid == 0) {
        float t = 0.f;
        #pragma unroll
        for (int w = 0; w < 32; w++) t += redb[w];
        sB = t;
    }
    __syncthreads();

    float acc = sB;
    const float* Pb = g_P + b * NGRP * CDIM + tid;
    #pragma unroll
    for (int g = 0; g < NGRP; g++)
        acc += sr[g] * (Pb[g * CDIM] - sm[g] * sGam[g]);
    g_s[b * CDIM + tid] = acc;
}

// ---------------------------------------------------------------------------
// GEMV core (R5-proven layout): out16[b,d] = in16[b,:].W[d,:] + bscale*bias[d]
// grid (128 d-tiles, 8 batch-groups), 256 thr, 8KB smem. One warp per d,
// 2-batch accumulators, full W row batched into registers (MLP=8).
// ---------------------------------------------------------------------------
__device__ __forceinline__ void gemv16_core(const float* __restrict__ in16,
                                            const float* __restrict__ W,
                                            const float* __restrict__ bias,
                                            float* __restrict__ out16,
                                            float bscale) {
    const int bg = blockIdx.y;           // batches 2*bg, 2*bg+1
    const int tid = threadIdx.x;
    const int wid = tid >> 5, lane = tid & 31;
    const int d = blockIdx.x * 8 + wid;

    __shared__ float ss[2 * CDIM];       // 8 KB

    const float4* wrow = reinterpret_cast<const float4*>(W + (size_t)d * CDIM);
    float4 wreg[8];
    #pragma unroll
    for (int j = 0; j < 8; j++) wreg[j] = wrow[lane + 32 * j];

    {
        const float4* src = reinterpret_cast<const float4*>(in16 + bg * 2 * CDIM);
        float4* dst = reinterpret_cast<float4*>(ss);
        #pragma unroll
        for (int m = 0; m < 2; m++) dst[tid + 256 * m] = src[tid + 256 * m];
    }
    __syncthreads();

    float acc[2] = {0.f, 0.f};
    #pragma unroll
    for (int j = 0; j < 8; j++) {
        const float4 wv = wreg[j];
        #pragma unroll
        for (int q = 0; q < 2; q++) {
            const float4 sv = reinterpret_cast<const float4*>(ss + q * CDIM)[lane + 32 * j];
            acc[q] += wv.x * sv.x + wv.y * sv.y + wv.z * sv.z + wv.w * sv.w;
        }
    }
    #pragma unroll
    for (int q = 0; q < 2; q++)
        #pragma unroll
        for (int o = 16; o; o >>= 1)
            acc[q] += __shfl_xor_sync(0xFFFFFFFFu, acc[q], o);

    if (lane == 0) {
        const float bs = bscale * bias[d];
        #pragma unroll
        for (int q = 0; q < 2; q++)
            out16[(bg * 2 + q) * CDIM + d] = acc[q] + bs;
    }
}

__global__ __launch_bounds__(256) void k3_gemv_v(const float* __restrict__ W,
                                                 const float* __restrict__ bias) {
    gemv16_core(g_s, W, bias, g_vsum, (float)NPOS);
}

__global__ __launch_bounds__(256) void k4a_gemv_o(const float* __restrict__ W,
                                                  const float* __restrict__ bias) {
    gemv16_core(g_vsum, W, bias, g_y, 1.0f);
}

// ---------------------------------------------------------------------------
// k4b: pure broadcast store — serial prologue is a single L2-hit LDG.32.
// One CTA per output row: out[b,d,:] = y[b,d]. 16384 CTAs x 128 thr,
// 2 STG.128 per thread. Measured-floor shape from R4 (~5.5+ TB/s drain).
// ---------------------------------------------------------------------------
__global__ __launch_bounds__(128) void k4b_bcast(float* __restrict__ out) {
    const int d = blockIdx.x;
    const int b = blockIdx.y;
    const float v = g_y[b * CDIM + d];
    const float4 vv = make_float4(v, v, v, v);
    float4* row = reinterpret_cast<float4*>(out + ((size_t)b * CDIM + d) * NPOS);
    row[threadIdx.x] = vv;
    row[threadIdx.x + 128] = vv;
}

extern "C" void kernel_launch(void* const* d_in, const int* in_sizes, int n_in,
                              void* d_out, int out_size) {
    const float* x     = (const float*)d_in[0];
    const float* gamma = (const float*)d_in[1];
    const float* beta  = (const float*)d_in[2];
    // d_in[3..6] = Wq,bq,Wk,bk : provably unused (softmax rows sum to 1).
    const float* Wv    = (const float*)d_in[7];
    const float* bv    = (const float*)d_in[8];
    const float* Wo    = (const float*)d_in[9];
    const float* bo    = (const float*)d_in[10];
    float* out = (float*)d_out;

    k1_stats<<<dim3(4, 8, BSZ), 256>>>(x, gamma);
    k2_colsum<<<BSZ, 1024>>>(gamma, beta);
    k3_gemv_v<<<dim3(CDIM / 8, 8), 256>>>(Wv, bv);
    k4a_gemv_o<<<dim3(CDIM / 8, 8), 256>>>(Wo, bo);
    k4b_bcast<<<dim3(CDIM, BSZ), 128>>>(out);
}

// round 9
// speedup vs baseline: 1.2375x; 1.2375x over previous
#include <cuda_runtime.h>

// Attention_72447508349519 — algebraic collapse:
//   softmax rows sum to 1 and einsum('bqk,bvd->bqd') contracts k and v
//   independently, so out[b,q,d] = sum_n v[b,n,d] for every q.
//   Pipeline (R7 base + L2 warm of Wv/Wo in k2):
//   k1 (stats+weighted colsums) -> k2 (fold groups, prefetch W) ->
//   k3 (GEMV Wv) -> k4 (GEMV Wo fused with 64MB broadcast store).
// Unused inputs: Wq,bq,Wk,bk.

#define BSZ   16
#define CDIM  1024
#define NPOS  1024
#define NGRP  32
#define GROWS 32
#define EPS   1e-5f

__device__ float g_P[BSZ * NGRP * CDIM];
__device__ float g_mean[BSZ * NGRP];
__device__ float g_rstd[BSZ * NGRP];
__device__ float g_s[BSZ * CDIM];
__device__ float g_vsum[BSZ * CDIM];

// ---------------------------------------------------------------------------
// k1 (R7-proven): per (b,g) block, one pass over the 1024x32 slab of x.
// fj/gq lane mapping: warp = 4 rows x 8 float4 slots -> every LDG.128 covers
// exactly 4 fully-used 128B lines (nL=4). Block 512, MLP=8 load batches.
// ---------------------------------------------------------------------------
#define PPITCH 1028   // bank = (4*fj + gq) mod 32 -> all 32 lanes distinct

__global__ __launch_bounds__(512) void k1_stats(const float* __restrict__ x,
                                                const float* __restrict__ gamma) {
    const int b = blockIdx.x >> 5;
    const int g = blockIdx.x & 31;
    const int tid = threadIdx.x;

    __shared__ float sg[GROWS];
    __shared__ float spw[8 * PPITCH];
    __shared__ float reds[16], redq[16];

    if (tid < GROWS) sg[tid] = gamma[g * GROWS + tid];
    __syncthreads();

    const int fj = tid & 7;    // float4 slot within the 32-float group row
    const int gq = tid >> 3;   // channel base (c = gq + 64*k), 0..63
    const float w0 = sg[fj * 4 + 0], w1 = sg[fj * 4 + 1];
    const float w2 = sg[fj * 4 + 2], w3 = sg[fj * 4 + 3];

    const float* xb = x + (size_t)b * CDIM * NPOS + g * GROWS;
    float* mypw = spw + fj * PPITCH;

    float tsum = 0.f, tsq = 0.f;
    #pragma unroll
    for (int k0 = 0; k0 < 16; k0 += 8) {
        float4 t[8];
        #pragma unroll
        for (int i = 0; i < 8; i++) {
            const int c = gq + 64 * (k0 + i);
            t[i] = reinterpret_cast<const float4*>(xb + (size_t)c * NPOS)[fj];
        }
        #pragma unroll
        for (int i = 0; i < 8; i++) {
            const int c = gq + 64 * (k0 + i);
            const float4 v = t[i];
            tsum += (v.x + v.y) + (v.z + v.w);
            tsq  += (v.x * v.x + v.y * v.y) + (v.z * v.z + v.w * v.w);
            mypw[c] = w0 * v.x + w1 * v.y + w2 * v.z + w3 * v.w;
        }
    }
    __syncthreads();

    // Fold the 8 fj-partials per channel (conflict-free, stride-1 c).
    float* Pout = g_P + (b * NGRP + g) * CDIM;
    #pragma unroll
    for (int m = 0; m < 2; m++) {
        const int c = tid + 512 * m;
        float acc = spw[c];
        #pragma unroll
        for (int f = 1; f < 8; f++) acc += spw[f * PPITCH + c];
        Pout[c] = acc;
    }

    // Block reduction for mean/rstd.
    #pragma unroll
    for (int o = 16; o; o >>= 1) {
        tsum += __shfl_xor_sync(0xFFFFFFFFu, tsum, o);
        tsq  += __shfl_xor_sync(0xFFFFFFFFu, tsq,  o);
    }
    const int wid = tid >> 5, lane = tid & 31;
    if (lane == 0) { reds[wid] = tsum; redq[wid] = tsq; }
    __syncthreads();
    if (tid == 0) {
        float S = 0.f, Q = 0.f;
        #pragma unroll
        for (int w = 0; w < 16; w++) { S += reds[w]; Q += redq[w]; }
        const float inv = 1.f / (float)(GROWS * CDIM);
        const float m = S * inv;
        const float var = Q * inv - m * m;
        g_mean[b * NGRP + g] = m;
        g_rstd[b * NGRP + g] = rsqrtf(var + EPS);
    }
}

// ---------------------------------------------------------------------------
// k2: s[b,c] = sum_g rstd[b,g]*(P[b,g,c] - mean[b,g]*Gam_g) + sum_n beta[n]
// NEW: warms Wv and Wo into L2 (each replay's 128MB x/out stream evicts them,
// making every GEMV head a cold DRAM read). 16 CTAs x 1024 thr each prefetch
// a disjoint 1/16 slice: 2 lines of Wv + 2 of Wo per thread, fire-and-forget.
// ---------------------------------------------------------------------------
__global__ __launch_bounds__(1024) void k2_colsum(const float* __restrict__ gamma,
                                                  const float* __restrict__ beta,
                                                  const float* __restrict__ Wv,
                                                  const float* __restrict__ Wo) {
    const int b = blockIdx.x;
    const int tid = threadIdx.x;

    // L2 warm: line index = b*2048 + tid*2 (+1); 16*1024*2 = 32768 lines = 4MB each.
    {
        const size_t off = ((size_t)b * 2048 + (size_t)tid * 2) * 32;  // floats
        const float* pv0 = Wv + off;
        const float* pv1 = Wv + off + 32;
        const float* po0 = Wo + off;
        const float* po1 = Wo + off + 32;
        asm volatile("prefetch.global.L2 [%0];" :: "l"(pv0));
        asm volatile("prefetch.global.L2 [%0];" :: "l"(pv1));
        asm volatile("prefetch.global.L2 [%0];" :: "l"(po0));
        asm volatile("prefetch.global.L2 [%0];" :: "l"(po1));
    }

    __shared__ float sgam[CDIM];
    __shared__ float sGam[NGRP];
    __shared__ float sm[NGRP], sr[NGRP];
    __shared__ float redb[32];
    __shared__ float sB;

    sgam[tid] = gamma[tid];
    float bb = beta[tid];
    #pragma unroll
    for (int o = 16; o; o >>= 1) bb += __shfl_xor_sync(0xFFFFFFFFu, bb, o);
    const int wid = tid >> 5, lane = tid & 31;
    if (lane == 0) redb[wid] = bb;
    if (tid < NGRP) { sm[tid] = g_mean[b * NGRP + tid]; sr[tid] = g_rstd[b * NGRP + tid]; }
    __syncthreads();

    if (tid < NGRP) {
        float t = 0.f;
        #pragma unroll
        for (int j = 0; j < GROWS; j++) t += sgam[tid * GROWS + j];
        sGam[tid] = t;
    }
    if (tid == 0) {
        float t = 0.f;
        #pragma unroll
        for (int w = 0; w < 32; w++) t += redb[w];
        sB = t;
    }
    __syncthreads();

    float acc = sB;
    const float* Pb = g_P + b * NGRP * CDIM + tid;
    #pragma unroll
    for (int g = 0; g < NGRP; g++)
        acc += sr[g] * (Pb[g * CDIM] - sm[g] * sGam[g]);
    g_s[b * CDIM + tid] = acc;
}

// ---------------------------------------------------------------------------
// k3: vsum[b,d] = s[b,:].Wv[d,:] + 1024*bv[d]
// grid (128 d-tiles, 8 batch-groups) = 1024 CTAs, 256 thr, 8KB smem.
// One warp per d, 2-batch accumulators; full W row batched into registers.
// ---------------------------------------------------------------------------
__global__ __launch_bounds__(256) void k3_gemv_v(const float* __restrict__ W,
                                                 const float* __restrict__ bias) {
    const int bg = blockIdx.y;           // batches 2*bg, 2*bg+1
    const int tid = threadIdx.x;
    const int wid = tid >> 5, lane = tid & 31;
    const int d = blockIdx.x * 8 + wid;

    __shared__ float ss[2 * CDIM];       // 8 KB

    const float4* wrow = reinterpret_cast<const float4*>(W + (size_t)d * CDIM);
    float4 wreg[8];
    #pragma unroll
    for (int j = 0; j < 8; j++) wreg[j] = wrow[lane + 32 * j];

    {
        const float4* src = reinterpret_cast<const float4*>(g_s + bg * 2 * CDIM);
        float4* dst = reinterpret_cast<float4*>(ss);
        #pragma unroll
        for (int m = 0; m < 2; m++) dst[tid + 256 * m] = src[tid + 256 * m];
    }
    __syncthreads();

    float acc[2] = {0.f, 0.f};
    #pragma unroll
    for (int j = 0; j < 8; j++) {
        const float4 wv = wreg[j];
        #pragma unroll
        for (int q = 0; q < 2; q++) {
            const float4 sv = reinterpret_cast<const float4*>(ss + q * CDIM)[lane + 32 * j];
            acc[q] += wv.x * sv.x + wv.y * sv.y + wv.z * sv.z + wv.w * sv.w;
        }
    }
    #pragma unroll
    for (int q = 0; q < 2; q++)
        #pragma unroll
        for (int o = 16; o; o >>= 1)
            acc[q] += __shfl_xor_sync(0xFFFFFFFFu, acc[q], o);

    if (lane == 0) {
        const float bs = (float)NPOS * bias[d];
        #pragma unroll
        for (int q = 0; q < 2; q++)
            g_vsum[(bg * 2 + q) * CDIM + d] = acc[q] + bs;
    }
}

// ---------------------------------------------------------------------------
// k4: y[b,d] = vsum[b,:].Wo[d,:] + bo[d], fused with the 64MB broadcast
// store out[b,d,:] = y[b,d]. grid (128, 8) = 1024 CTAs; W head now L2-hit
// thanks to k2's prefetch. Each warp stores two 4KB rows.
// ---------------------------------------------------------------------------
__global__ __launch_bounds__(256) void k4_gemv_o_bcast(const float* __restrict__ W,
                                                       const float* __restrict__ bias,
                                                       float* __restrict__ out) {
    const int bg = blockIdx.y;           // batches 2*bg, 2*bg+1
    const int tid = threadIdx.x;
    const int wid = tid >> 5, lane = tid & 31;
    const int d = blockIdx.x * 8 + wid;

    __shared__ float ss[2 * CDIM];       // 8 KB

    const float4* wrow = reinterpret_cast<const float4*>(W + (size_t)d * CDIM);
    float4 wreg[8];
    #pragma unroll
    for (int j = 0; j < 8; j++) wreg[j] = wrow[lane + 32 * j];

    {
        const float4* src = reinterpret_cast<const float4*>(g_vsum + bg * 2 * CDIM);
        float4* dst = reinterpret_cast<float4*>(ss);
        #pragma unroll
        for (int m = 0; m < 2; m++) dst[tid + 256 * m] = src[tid + 256 * m];
    }
    __syncthreads();

    float acc[2] = {0.f, 0.f};
    #pragma unroll
    for (int j = 0; j < 8; j++) {
        const float4 wv = wreg[j];
        #pragma unroll
        for (int q = 0; q < 2; q++) {
            const float4 sv = reinterpret_cast<const float4*>(ss + q * CDIM)[lane + 32 * j];
            acc[q] += wv.x * sv.x + wv.y * sv.y + wv.z * sv.z + wv.w * sv.w;
        }
    }
    // Butterfly: every lane ends with the full sum -> whole warp streams stores.
    #pragma unroll
    for (int q = 0; q < 2; q++)
        #pragma unroll
        for (int o = 16; o; o >>= 1)
            acc[q] += __shfl_xor_sync(0xFFFFFFFFu, acc[q], o);

    const float bs = bias[d];
    #pragma unroll
    for (int q = 0; q < 2; q++) {
        const float v = acc[q] + bs;
        const float4 vv = make_float4(v, v, v, v);
        float4* row = reinterpret_cast<float4*>(
            out + ((size_t)((bg * 2 + q) * CDIM + d)) * NPOS);
        #pragma unroll
        for (int t = 0; t < 8; t++) row[lane + 32 * t] = vv;
    }
}

extern "C" void kernel_launch(void* const* d_in, const int* in_sizes, int n_in,
                              void* d_out, int out_size) {
    const float* x     = (const float*)d_in[0];
    const float* gamma = (const float*)d_in[1];
    const float* beta  = (const float*)d_in[2];
    // d_in[3..6] = Wq,bq,Wk,bk : provably unused (softmax rows sum to 1).
    const float* Wv    = (const float*)d_in[7];
    const float* bv    = (const float*)d_in[8];
    const float* Wo    = (const float*)d_in[9];
    const float* bo    = (const float*)d_in[10];
    float* out = (float*)d_out;

    k1_stats<<<BSZ * NGRP, 512>>>(x, gamma);
    k2_colsum<<<BSZ, 1024>>>(gamma, beta, Wv, Wo);
    k3_gemv_v<<<dim3(CDIM / 8, 8), 256>>>(Wv, bv);
    k4_gemv_o_bcast<<<dim3(CDIM / 8, 8), 256>>>(Wo, bo, out);
}

// round 10
// speedup vs baseline: 1.3680x; 1.1055x over previous
#include <cuda_runtime.h>

// Attention_72447508349519 — algebraic collapse:
//   softmax rows sum to 1 and einsum('bqk,bvd->bqd') contracts k and v
//   independently, so out[b,q,d] = sum_n v[b,n,d] for every q.
//   Pipeline (R7 structure + streaming cache hints):
//   k1 (stats+weighted colsums, x via __ldcs) -> k2 (fold groups) ->
//   k3 (GEMV Wv) -> k4 (GEMV Wo fused with 64MB broadcast store via __stcs).
//   Hints keep Wv/Wo L2-resident across graph replays and drain the output
//   writeback during k4 instead of during the next replay's read phase.
// Unused inputs: Wq,bq,Wk,bk.

#define BSZ   16
#define CDIM  1024
#define NPOS  1024
#define NGRP  32
#define GROWS 32
#define EPS   1e-5f

__device__ float g_P[BSZ * NGRP * CDIM];
__device__ float g_mean[BSZ * NGRP];
__device__ float g_rstd[BSZ * NGRP];
__device__ float g_s[BSZ * CDIM];
__device__ float g_vsum[BSZ * CDIM];

// ---------------------------------------------------------------------------
// k1 (R7-proven): per (b,g) block, one pass over the 1024x32 slab of x.
// fj/gq lane mapping: warp = 4 rows x 8 float4 slots -> every LDG.128 covers
// exactly 4 fully-used 128B lines (nL=4). Block 512, MLP=8 load batches.
// x loads + P stores are streaming (evict-first): never claim L2 residency.
// ---------------------------------------------------------------------------
#define PPITCH 1028   // bank = (4*fj + gq) mod 32 -> all 32 lanes distinct

__global__ __launch_bounds__(512) void k1_stats(const float* __restrict__ x,
                                                const float* __restrict__ gamma) {
    const int b = blockIdx.x >> 5;
    const int g = blockIdx.x & 31;
    const int tid = threadIdx.x;

    __shared__ float sg[GROWS];
    __shared__ float spw[8 * PPITCH];
    __shared__ float reds[16], redq[16];

    if (tid < GROWS) sg[tid] = gamma[g * GROWS + tid];
    __syncthreads();

    const int fj = tid & 7;    // float4 slot within the 32-float group row
    const int gq = tid >> 3;   // channel base (c = gq + 64*k), 0..63
    const float w0 = sg[fj * 4 + 0], w1 = sg[fj * 4 + 1];
    const float w2 = sg[fj * 4 + 2], w3 = sg[fj * 4 + 3];

    const float* xb = x + (size_t)b * CDIM * NPOS + g * GROWS;
    float* mypw = spw + fj * PPITCH;

    float tsum = 0.f, tsq = 0.f;
    #pragma unroll
    for (int k0 = 0; k0 < 16; k0 += 8) {
        float4 t[8];
        #pragma unroll
        for (int i = 0; i < 8; i++) {
            const int c = gq + 64 * (k0 + i);
            t[i] = __ldcs(&reinterpret_cast<const float4*>(xb + (size_t)c * NPOS)[fj]);
        }
        #pragma unroll
        for (int i = 0; i < 8; i++) {
            const int c = gq + 64 * (k0 + i);
            const float4 v = t[i];
            tsum += (v.x + v.y) + (v.z + v.w);
            tsq  += (v.x * v.x + v.y * v.y) + (v.z * v.z + v.w * v.w);
            mypw[c] = w0 * v.x + w1 * v.y + w2 * v.z + w3 * v.w;
        }
    }
    __syncthreads();

    // Fold the 8 fj-partials per channel (conflict-free, stride-1 c).
    float* Pout = g_P + (b * NGRP + g) * CDIM;
    #pragma unroll
    for (int m = 0; m < 2; m++) {
        const int c = tid + 512 * m;
        float acc = spw[c];
        #pragma unroll
        for (int f = 1; f < 8; f++) acc += spw[f * PPITCH + c];
        __stcs(&Pout[c], acc);
    }

    // Block reduction for mean/rstd.
    #pragma unroll
    for (int o = 16; o; o >>= 1) {
        tsum += __shfl_xor_sync(0xFFFFFFFFu, tsum, o);
        tsq  += __shfl_xor_sync(0xFFFFFFFFu, tsq,  o);
    }
    const int wid = tid >> 5, lane = tid & 31;
    if (lane == 0) { reds[wid] = tsum; redq[wid] = tsq; }
    __syncthreads();
    if (tid == 0) {
        float S = 0.f, Q = 0.f;
        #pragma unroll
        for (int w = 0; w < 16; w++) { S += reds[w]; Q += redq[w]; }
        const float inv = 1.f / (float)(GROWS * CDIM);
        const float m = S * inv;
        const float var = Q * inv - m * m;
        g_mean[b * NGRP + g] = m;
        g_rstd[b * NGRP + g] = rsqrtf(var + EPS);
    }
}

// ---------------------------------------------------------------------------
// k2: s[b,c] = sum_g rstd[b,g]*(P[b,g,c] - mean[b,g]*Gam_g) + sum_n beta[n]
// P loads streaming (read-once scratch).
// ---------------------------------------------------------------------------
__global__ __launch_bounds__(1024) void k2_colsum(const float* __restrict__ gamma,
                                                  const float* __restrict__ beta) {
    const int b = blockIdx.x;
    const int tid = threadIdx.x;

    __shared__ float sgam[CDIM];
    __shared__ float sGam[NGRP];
    __shared__ float sm[NGRP], sr[NGRP];
    __shared__ float redb[32];
    __shared__ float sB;

    sgam[tid] = gamma[tid];
    float bb = beta[tid];
    #pragma unroll
    for (int o = 16; o; o >>= 1) bb += __shfl_xor_sync(0xFFFFFFFFu, bb, o);
    const int wid = tid >> 5, lane = tid & 31;
    if (lane == 0) redb[wid] = bb;
    if (tid < NGRP) { sm[tid] = g_mean[b * NGRP + tid]; sr[tid] = g_rstd[b * NGRP + tid]; }
    __syncthreads();

    if (tid < NGRP) {
        float t = 0.f;
        #pragma unroll
        for (int j = 0; j < GROWS; j++) t += sgam[tid * GROWS + j];
        sGam[tid] = t;
    }
    if (tid == 0) {
        float t = 0.f;
        #pragma unroll
        for (int w = 0; w < 32; w++) t += redb[w];
        sB = t;
    }
    __syncthreads();

    float acc = sB;
    const float* Pb = g_P + b * NGRP * CDIM + tid;
    #pragma unroll
    for (int g = 0; g < NGRP; g++)
        acc += sr[g] * (__ldcs(&Pb[g * CDIM]) - sm[g] * sGam[g]);
    g_s[b * CDIM + tid] = acc;
}

// ---------------------------------------------------------------------------
// k3: vsum[b,d] = s[b,:].Wv[d,:] + 1024*bv[d]
// grid (128 d-tiles, 8 batch-groups) = 1024 CTAs, 256 thr, 8KB smem.
// W loads default policy -> with x/out streaming-hinted, W stays L2-resident
// across replays and these become L2 hits.
// ---------------------------------------------------------------------------
__global__ __launch_bounds__(256) void k3_gemv_v(const float* __restrict__ W,
                                                 const float* __restrict__ bias) {
    const int bg = blockIdx.y;           // batches 2*bg, 2*bg+1
    const int tid = threadIdx.x;
    const int wid = tid >> 5, lane = tid & 31;
    const int d = blockIdx.x * 8 + wid;

    __shared__ float ss[2 * CDIM];       // 8 KB

    const float4* wrow = reinterpret_cast<const float4*>(W + (size_t)d * CDIM);
    float4 wreg[8];
    #pragma unroll
    for (int j = 0; j < 8; j++) wreg[j] = wrow[lane + 32 * j];

    {
        const float4* src = reinterpret_cast<const float4*>(g_s + bg * 2 * CDIM);
        float4* dst = reinterpret_cast<float4*>(ss);
        #pragma unroll
        for (int m = 0; m < 2; m++) dst[tid + 256 * m] = src[tid + 256 * m];
    }
    __syncthreads();

    float acc[2] = {0.f, 0.f};
    #pragma unroll
    for (int j = 0; j < 8; j++) {
        const float4 wv = wreg[j];
        #pragma unroll
        for (int q = 0; q < 2; q++) {
            const float4 sv = reinterpret_cast<const float4*>(ss + q * CDIM)[lane + 32 * j];
            acc[q] += wv.x * sv.x + wv.y * sv.y + wv.z * sv.z + wv.w * sv.w;
        }
    }
    #pragma unroll
    for (int q = 0; q < 2; q++)
        #pragma unroll
        for (int o = 16; o; o >>= 1)
            acc[q] += __shfl_xor_sync(0xFFFFFFFFu, acc[q], o);

    if (lane == 0) {
        const float bs = (float)NPOS * bias[d];
        #pragma unroll
        for (int q = 0; q < 2; q++)
            g_vsum[(bg * 2 + q) * CDIM + d] = acc[q] + bs;
    }
}

// ---------------------------------------------------------------------------
// k4: y[b,d] = vsum[b,:].Wo[d,:] + bo[d], fused with the 64MB broadcast
// store out[b,d,:] = y[b,d] via __stcs (evict-first: writeback drains during
// k4's own window, not the next replay's read phase). grid (128, 8).
// ---------------------------------------------------------------------------
__global__ __launch_bounds__(256) void k4_gemv_o_bcast(const float* __restrict__ W,
                                                       const float* __restrict__ bias,
                                                       float* __restrict__ out) {
    const int bg = blockIdx.y;           // batches 2*bg, 2*bg+1
    const int tid = threadIdx.x;
    const int wid = tid >> 5, lane = tid & 31;
    const int d = blockIdx.x * 8 + wid;

    __shared__ float ss[2 * CDIM];       // 8 KB

    const float4* wrow = reinterpret_cast<const float4*>(W + (size_t)d * CDIM);
    float4 wreg[8];
    #pragma unroll
    for (int j = 0; j < 8; j++) wreg[j] = wrow[lane + 32 * j];

    {
        const float4* src = reinterpret_cast<const float4*>(g_vsum + bg * 2 * CDIM);
        float4* dst = reinterpret_cast<float4*>(ss);
        #pragma unroll
        for (int m = 0; m < 2; m++) dst[tid + 256 * m] = src[tid + 256 * m];
    }
    __syncthreads();

    float acc[2] = {0.f, 0.f};
    #pragma unroll
    for (int j = 0; j < 8; j++) {
        const float4 wv = wreg[j];
        #pragma unroll
        for (int q = 0; q < 2; q++) {
            const float4 sv = reinterpret_cast<const float4*>(ss + q * CDIM)[lane + 32 * j];
            acc[q] += wv.x * sv.x + wv.y * sv.y + wv.z * sv.z + wv.w * sv.w;
        }
    }
    // Butterfly: every lane ends with the full sum -> whole warp streams stores.
    #pragma unroll
    for (int q = 0; q < 2; q++)
        #pragma unroll
        for (int o = 16; o; o >>= 1)
            acc[q] += __shfl_xor_sync(0xFFFFFFFFu, acc[q], o);

    const float bs = bias[d];
    #pragma unroll
    for (int q = 0; q < 2; q++) {
        const float v = acc[q] + bs;
        const float4 vv = make_float4(v, v, v, v);
        float4* row = reinterpret_cast<float4*>(
            out + ((size_t)((bg * 2 + q) * CDIM + d)) * NPOS);
        #pragma unroll
        for (int t = 0; t < 8; t++) __stcs(&row[lane + 32 * t], vv);
    }
}

extern "C" void kernel_launch(void* const* d_in, const int* in_sizes, int n_in,
                              void* d_out, int out_size) {
    const float* x     = (const float*)d_in[0];
    const float* gamma = (const float*)d_in[1];
    const float* beta  = (const float*)d_in[2];
    // d_in[3..6] = Wq,bq,Wk,bk : provably unused (softmax rows sum to 1).
    const float* Wv    = (const float*)d_in[7];
    const float* bv    = (const float*)d_in[8];
    const float* Wo    = (const float*)d_in[9];
    const float* bo    = (const float*)d_in[10];
    float* out = (float*)d_out;

    k1_stats<<<BSZ * NGRP, 512>>>(x, gamma);
    k2_colsum<<<BSZ, 1024>>>(gamma, beta);
    k3_gemv_v<<<dim3(CDIM / 8, 8), 256>>>(Wv, bv);
    k4_gemv_o_bcast<<<dim3(CDIM / 8, 8), 256>>>(Wo, bo, out);
}